// round 1
// baseline (speedup 1.0000x reference)
#include <cuda_runtime.h>
#include <cuda_bf16.h>
#include <cstdint>

// Problem constants
#define BB 4
#define CC 3
#define HH 384
#define WW 384
#define KK 5
#define K2 25
#define HWSZ (HH * WW)          // 147456
#define NUM_ITER 20
#define INVZ2 44.4444444444444444f   // 1 / 0.15^2

// Tile shape: 32 x 8 pixels per block, halo 2 each side
#define TX 32
#define TY 8
#define LX (TX + 4)   // 36
#define LY (TY + 4)   // 12

// Scratch: normalized weights (59 MB) + ping-pong x buffers
__device__ float g_w[(size_t)BB * K2 * HWSZ];
__device__ float g_x[2][(size_t)BB * HWSZ];

// ---------------------------------------------------------------------------
// Kernel 1: compute normalized bilateral weights w[b,k,h,w] = aff / sumz,
// and initialize x0 = feat * mask.
// img is shifted by +10 BEFORE zero padding (matches reference), so OOB taps
// use padded value 0 and their affinity underflows to exactly 0.
// ---------------------------------------------------------------------------
__global__ void __launch_bounds__(256) precompute_kernel(
    const float* __restrict__ img,
    const float* __restrict__ feat,
    const float* __restrict__ mask)
{
    __shared__ float s[LY][LX][CC];

    const int b  = blockIdx.z;
    const int h0 = blockIdx.y * TY;
    const int w0 = blockIdx.x * TX;
    const int tx = threadIdx.x, ty = threadIdx.y;
    const int tid = ty * TX + tx;

    const float* imb = img + (size_t)b * CC * HWSZ;

    // Load shifted img tile + halo into smem (OOB = 0, the padded value)
    for (int i = tid; i < LY * LX; i += TX * TY) {
        int ly = i / LX, lx = i - ly * LX;
        int gh = h0 + ly - 2, gw = w0 + lx - 2;
        bool ok = (gh >= 0) && (gh < HH) && (gw >= 0) && (gw < WW);
        #pragma unroll
        for (int c = 0; c < CC; c++)
            s[ly][lx][c] = ok ? imb[(size_t)c * HWSZ + gh * WW + gw] + 10.0f : 0.0f;
    }
    __syncthreads();

    const float c0 = s[ty + 2][tx + 2][0];
    const float c1 = s[ty + 2][tx + 2][1];
    const float c2 = s[ty + 2][tx + 2][2];

    float aff[K2];
    float sum = 0.0f;
    #pragma unroll
    for (int k = 0; k < K2; k++) {
        const int dy = k / KK, dx = k % KK;
        float d0 = s[ty + dy][tx + dx][0] - c0;
        float d1 = s[ty + dy][tx + dx][1] - c1;
        float d2 = s[ty + dy][tx + dx][2] - c2;
        float d  = d0 * d0 + d1 * d1 + d2 * d2;
        float a  = __expf(-d * INVZ2);
        aff[k] = a;
        sum += a;
    }
    const float inv = 1.0f / (sum + 1e-10f);

    const int gh = h0 + ty, gw = w0 + tx;
    const size_t pix = (size_t)gh * WW + gw;
    float* wb = g_w + (size_t)b * K2 * HWSZ + pix;
    #pragma unroll
    for (int k = 0; k < K2; k++)
        wb[(size_t)k * HWSZ] = aff[k] * inv;

    const size_t p = (size_t)b * HWSZ + pix;
    g_x[0][p] = feat[p] * mask[p];
}

// ---------------------------------------------------------------------------
// Kernel 2: one propagation step
//   x_out[p] = mask[p] * sum_k w[p,k] * x_in[p + off_k]   (zero-padded gather)
// ---------------------------------------------------------------------------
__global__ void __launch_bounds__(256) iter_kernel(
    const float* __restrict__ mask,
    float* __restrict__ out,   // used only when writeOut != 0 (final iter)
    int src, int writeOut)
{
    __shared__ float s[LY][LX];

    const int b  = blockIdx.z;
    const int h0 = blockIdx.y * TY;
    const int w0 = blockIdx.x * TX;
    const int tx = threadIdx.x, ty = threadIdx.y;
    const int tid = ty * TX + tx;

    const float* xin = g_x[src] + (size_t)b * HWSZ;

    for (int i = tid; i < LY * LX; i += TX * TY) {
        int ly = i / LX, lx = i - ly * LX;
        int gh = h0 + ly - 2, gw = w0 + lx - 2;
        bool ok = (gh >= 0) && (gh < HH) && (gw >= 0) && (gw < WW);
        s[ly][lx] = ok ? xin[gh * WW + gw] : 0.0f;
    }
    __syncthreads();

    const int gh = h0 + ty, gw = w0 + tx;
    const size_t pix = (size_t)gh * WW + gw;
    const float* wb = g_w + (size_t)b * K2 * HWSZ + pix;

    float acc = 0.0f;
    #pragma unroll
    for (int k = 0; k < K2; k++) {
        const int dy = k / KK, dx = k % KK;
        acc += wb[(size_t)k * HWSZ] * s[ty + dy][tx + dx];
    }

    const size_t p = (size_t)b * HWSZ + pix;
    float* xo = writeOut ? out : g_x[1 - src];
    xo[p] = acc * mask[p];
}

// ---------------------------------------------------------------------------
extern "C" void kernel_launch(void* const* d_in, const int* in_sizes, int n_in,
                              void* d_out, int out_size)
{
    const float* img  = (const float*)d_in[0];
    const float* feat = (const float*)d_in[1];
    const float* mask = (const float*)d_in[2];
    float* out = (float*)d_out;

    dim3 blk(TX, TY);
    dim3 grd(WW / TX, HH / TY, BB);   // (12, 48, 4)

    precompute_kernel<<<grd, blk>>>(img, feat, mask);

    for (int i = 0; i < NUM_ITER; i++) {
        int src = i & 1;
        int writeOut = (i == NUM_ITER - 1) ? 1 : 0;
        iter_kernel<<<grd, blk>>>(mask, out, src, writeOut);
    }
}

// round 2
// speedup vs baseline: 1.0412x; 1.0412x over previous
#include <cuda_runtime.h>
#include <cuda_fp16.h>
#include <cstdint>

// Problem constants
#define BB 4
#define CC 3
#define HH 384
#define WW 384
#define KK 5
#define K2 25
#define HWSZ (HH * WW)          // 147456
#define NUM_ITER 20
#define INVZ2 44.4444444444444444f   // 1 / 0.15^2

// Tile shape: 32 x 16 pixels per block, halo 2 each side
#define TX 32
#define TY 16
#define LX (TX + 4)   // 36
#define LY (TY + 4)   // 20

// Scratch:
//  g_w2 : 12 half2 planes per batch (taps 0..23, pairs)  -> 28.3 MB
//  g_w1 : 1 half plane per batch (tap 24)                ->  1.2 MB
//  g_x  : ping-pong x buffers (fp32)
__device__ __half2 g_w2[(size_t)BB * 12 * HWSZ];
__device__ __half  g_w1[(size_t)BB * HWSZ];
__device__ float   g_x[2][(size_t)BB * HWSZ];

// ---------------------------------------------------------------------------
// Kernel 1: compute normalized bilateral weights, quantize to fp16, and
// initialize x0 = feat * mask.
// img is shifted by +10 BEFORE zero padding (matches reference), so OOB taps
// use padded value 0 and their affinity underflows to exactly 0.
// ---------------------------------------------------------------------------
__global__ void __launch_bounds__(512) precompute_kernel(
    const float* __restrict__ img,
    const float* __restrict__ feat,
    const float* __restrict__ mask)
{
    __shared__ float s[LY][LX][CC];

    const int b  = blockIdx.z;
    const int h0 = blockIdx.y * TY;
    const int w0 = blockIdx.x * TX;
    const int tx = threadIdx.x, ty = threadIdx.y;
    const int tid = ty * TX + tx;

    const float* imb = img + (size_t)b * CC * HWSZ;

    for (int i = tid; i < LY * LX; i += TX * TY) {
        int ly = i / LX, lx = i - ly * LX;
        int gh = h0 + ly - 2, gw = w0 + lx - 2;
        bool ok = (gh >= 0) && (gh < HH) && (gw >= 0) && (gw < WW);
        #pragma unroll
        for (int c = 0; c < CC; c++)
            s[ly][lx][c] = ok ? imb[(size_t)c * HWSZ + gh * WW + gw] + 10.0f : 0.0f;
    }
    __syncthreads();

    const float c0 = s[ty + 2][tx + 2][0];
    const float c1 = s[ty + 2][tx + 2][1];
    const float c2 = s[ty + 2][tx + 2][2];

    float aff[K2];
    float sum = 0.0f;
    #pragma unroll
    for (int k = 0; k < K2; k++) {
        const int dy = k / KK, dx = k % KK;
        float d0 = s[ty + dy][tx + dx][0] - c0;
        float d1 = s[ty + dy][tx + dx][1] - c1;
        float d2 = s[ty + dy][tx + dx][2] - c2;
        float d  = d0 * d0 + d1 * d1 + d2 * d2;
        float a  = __expf(-d * INVZ2);
        aff[k] = a;
        sum += a;
    }
    const float inv = 1.0f / (sum + 1e-10f);

    const int gh = h0 + ty, gw = w0 + tx;
    const size_t pix = (size_t)gh * WW + gw;

    __half2* w2 = g_w2 + (size_t)b * 12 * HWSZ + pix;
    #pragma unroll
    for (int j = 0; j < 12; j++)
        w2[(size_t)j * HWSZ] = __floats2half2_rn(aff[2 * j] * inv, aff[2 * j + 1] * inv);
    g_w1[(size_t)b * HWSZ + pix] = __float2half_rn(aff[24] * inv);

    const size_t p = (size_t)b * HWSZ + pix;
    g_x[0][p] = feat[p] * mask[p];
}

// ---------------------------------------------------------------------------
// Kernel 2: one propagation step with in-kernel renormalization:
//   x_out[p] = mask[p] * (sum_k q_k * x_in[p+off_k]) / (sum_k q_k)
// where q_k are the fp16-quantized normalized weights. Renormalizing by the
// quantized sum restores the exact averaging property, so fp16 error does not
// compound as a systematic bias across the 20 iterations.
// ---------------------------------------------------------------------------
__global__ void __launch_bounds__(512) iter_kernel(
    const float* __restrict__ mask,
    float* __restrict__ out,   // used only when writeOut != 0 (final iter)
    int src, int writeOut)
{
    __shared__ float s[LY][LX];

    const int b  = blockIdx.z;
    const int h0 = blockIdx.y * TY;
    const int w0 = blockIdx.x * TX;
    const int tx = threadIdx.x, ty = threadIdx.y;
    const int tid = ty * TX + tx;

    const float* xin = g_x[src] + (size_t)b * HWSZ;

    for (int i = tid; i < LY * LX; i += TX * TY) {
        int ly = i / LX, lx = i - ly * LX;
        int gh = h0 + ly - 2, gw = w0 + lx - 2;
        bool ok = (gh >= 0) && (gh < HH) && (gw >= 0) && (gw < WW);
        s[ly][lx] = ok ? xin[gh * WW + gw] : 0.0f;
    }
    __syncthreads();

    const int gh = h0 + ty, gw = w0 + tx;
    const size_t pix = (size_t)gh * WW + gw;

    const __half2* w2 = g_w2 + (size_t)b * 12 * HWSZ + pix;

    float acc = 0.0f;
    float ws  = 0.0f;
    #pragma unroll
    for (int j = 0; j < 12; j++) {
        float2 f = __half22float2(w2[(size_t)j * HWSZ]);
        const int k0 = 2 * j, k1 = 2 * j + 1;
        const int dy0 = k0 / KK, dx0 = k0 % KK;
        const int dy1 = k1 / KK, dx1 = k1 % KK;
        acc += f.x * s[ty + dy0][tx + dx0];
        acc += f.y * s[ty + dy1][tx + dx1];
        ws  += f.x + f.y;
    }
    {
        float f = __half2float(g_w1[(size_t)b * HWSZ + pix]);
        acc += f * s[ty + 4][tx + 4];
        ws  += f;
    }

    const float r = __fdividef(acc, ws);

    const size_t p = (size_t)b * HWSZ + pix;
    float* xo = writeOut ? out : g_x[1 - src];
    xo[p] = r * mask[p];
}

// ---------------------------------------------------------------------------
extern "C" void kernel_launch(void* const* d_in, const int* in_sizes, int n_in,
                              void* d_out, int out_size)
{
    const float* img  = (const float*)d_in[0];
    const float* feat = (const float*)d_in[1];
    const float* mask = (const float*)d_in[2];
    float* out = (float*)d_out;

    dim3 blk(TX, TY);
    dim3 grd(WW / TX, HH / TY, BB);   // (12, 24, 4)

    precompute_kernel<<<grd, blk>>>(img, feat, mask);

    for (int i = 0; i < NUM_ITER; i++) {
        int src = i & 1;
        int writeOut = (i == NUM_ITER - 1) ? 1 : 0;
        iter_kernel<<<grd, blk>>>(mask, out, src, writeOut);
    }
}

// round 3
// speedup vs baseline: 1.2750x; 1.2246x over previous
#include <cuda_runtime.h>
#include <cuda_fp16.h>
#include <cstdint>

// Problem constants
#define BB 4
#define CC 3
#define HH 384
#define WW 384
#define KK 5
#define K2 25
#define HWSZ (HH * WW)          // 147456
#define NUM_ITER 20
#define INVZ2 44.4444444444444444f   // 1 / 0.15^2

// ---------------- precompute tile (unchanged from R2) ----------------
#define PTX 32
#define PTY 16
#define PLX (PTX + 4)
#define PLY (PTY + 4)

// ---------------- iter tile: 64x16 pixels, 32x16 threads (2 px/thread) ----
#define TXV 32
#define TYV 16
#define PW  64                  // pixel width of tile
#define RLX (PW + 4)            // 68 floats per smem row (even -> float2 aligned)
#define RLY (TYV + 4)           // 20 rows

// Scratch:
//  g_w2 : 12 half2 planes per batch (taps 0..23 paired per pixel) -> 28.3 MB
//  g_w1 : 1 half plane per batch (tap 24)                         ->  1.2 MB
//  g_x  : ping-pong x buffers (fp32)
__device__ __half2 g_w2[(size_t)BB * 12 * HWSZ];
__device__ __half  g_w1[(size_t)BB * HWSZ];
__device__ float   g_x[2][(size_t)BB * HWSZ];

// ---------------------------------------------------------------------------
// Kernel 1: normalized bilateral weights -> fp16, x0 = feat * mask.
// img shifted by +10 BEFORE zero padding (matches reference): OOB taps use
// padded value 0 and their affinity underflows to exactly 0.
// ---------------------------------------------------------------------------
__global__ void __launch_bounds__(512) precompute_kernel(
    const float* __restrict__ img,
    const float* __restrict__ feat,
    const float* __restrict__ mask)
{
    __shared__ float s[PLY][PLX][CC];

    const int b  = blockIdx.z;
    const int h0 = blockIdx.y * PTY;
    const int w0 = blockIdx.x * PTX;
    const int tx = threadIdx.x, ty = threadIdx.y;
    const int tid = ty * PTX + tx;

    const float* imb = img + (size_t)b * CC * HWSZ;

    for (int i = tid; i < PLY * PLX; i += PTX * PTY) {
        int ly = i / PLX, lx = i - ly * PLX;
        int gh = h0 + ly - 2, gw = w0 + lx - 2;
        bool ok = (gh >= 0) && (gh < HH) && (gw >= 0) && (gw < WW);
        #pragma unroll
        for (int c = 0; c < CC; c++)
            s[ly][lx][c] = ok ? imb[(size_t)c * HWSZ + gh * WW + gw] + 10.0f : 0.0f;
    }
    __syncthreads();

    const float c0 = s[ty + 2][tx + 2][0];
    const float c1 = s[ty + 2][tx + 2][1];
    const float c2 = s[ty + 2][tx + 2][2];

    float aff[K2];
    float sum = 0.0f;
    #pragma unroll
    for (int k = 0; k < K2; k++) {
        const int dy = k / KK, dx = k % KK;
        float d0 = s[ty + dy][tx + dx][0] - c0;
        float d1 = s[ty + dy][tx + dx][1] - c1;
        float d2 = s[ty + dy][tx + dx][2] - c2;
        float d  = d0 * d0 + d1 * d1 + d2 * d2;
        float a  = __expf(-d * INVZ2);
        aff[k] = a;
        sum += a;
    }
    const float inv = 1.0f / (sum + 1e-10f);

    const int gh = h0 + ty, gw = w0 + tx;
    const size_t pix = (size_t)gh * WW + gw;

    __half2* w2 = g_w2 + (size_t)b * 12 * HWSZ + pix;
    #pragma unroll
    for (int j = 0; j < 12; j++)
        w2[(size_t)j * HWSZ] = __floats2half2_rn(aff[2 * j] * inv, aff[2 * j + 1] * inv);
    g_w1[(size_t)b * HWSZ + pix] = __float2half_rn(aff[24] * inv);

    const size_t p = (size_t)b * HWSZ + pix;
    g_x[0][p] = feat[p] * mask[p];
}

// ---------------------------------------------------------------------------
// Kernel 2: one propagation step, 2 adjacent pixels per thread, with in-kernel
// renormalization (acc/ws) so fp16 weight error doesn't compound.
// ---------------------------------------------------------------------------
__global__ void __launch_bounds__(512) iter_kernel(
    const float* __restrict__ mask,
    float* __restrict__ out,   // used only when writeOut != 0 (final iter)
    int src, int writeOut)
{
    __shared__ float s[RLY][RLX];   // 68 floats/row, 8B-aligned rows

    const int b  = blockIdx.z;
    const int h0 = blockIdx.y * TYV;
    const int w0 = blockIdx.x * PW;
    const int tx = threadIdx.x, ty = threadIdx.y;
    const int tid = ty * TXV + tx;

    const float* xin = g_x[src] + (size_t)b * HWSZ;

    // Load x tile + halo (region [h0-2, h0+18) x [w0-2, w0+66))
    for (int i = tid; i < RLY * RLX; i += TXV * TYV) {
        int ly = i / RLX, lx = i - ly * RLX;
        int gh = h0 + ly - 2, gw = w0 + lx - 2;
        bool ok = (gh >= 0) && (gh < HH) && (gw >= 0) && (gw < WW);
        s[ly][lx] = ok ? xin[gh * WW + gw] : 0.0f;
    }
    __syncthreads();

    const int gh  = h0 + ty;
    const int wc  = w0 + 2 * tx;                  // even -> all vector loads aligned
    const size_t pix = (size_t)gh * WW + wc;

    // Preload all weight planes for both pixels (float2 = 2 x half2)
    const __half2* wbase = g_w2 + (size_t)b * 12 * HWSZ + pix;
    float2 Wj[12];
    #pragma unroll
    for (int j = 0; j < 12; j++)
        Wj[j] = *reinterpret_cast<const float2*>(wbase + (size_t)j * HWSZ);
    const __half2 w24 = *reinterpret_cast<const __half2*>(g_w1 + (size_t)b * HWSZ + pix);

    float acc0 = 0.f, ws0 = 0.f, acc1 = 0.f, ws1 = 0.f;

    #pragma unroll
    for (int dy = 0; dy < KK; dy++) {
        // 6 contiguous taps covering both pixels' 5-tap row: local floats
        // [2tx .. 2tx+5] = float2 indices tx, tx+1, tx+2 (conflict-free LDS.64)
        const float2* r = reinterpret_cast<const float2*>(&s[ty + dy][0]) + tx;
        float2 va = r[0], vb = r[1], vc = r[2];
        float v[6] = { va.x, va.y, vb.x, vb.y, vc.x, vc.y };

        #pragma unroll
        for (int dx = 0; dx < KK; dx++) {
            const int k = dy * KK + dx;
            float wA, wB;
            if (k < 24) {
                const int j = k >> 1;
                __half2 hA = *reinterpret_cast<const __half2*>(&Wj[j].x);
                __half2 hB = *reinterpret_cast<const __half2*>(&Wj[j].y);
                if (k & 1) { wA = __high2float(hA); wB = __high2float(hB); }
                else       { wA = __low2float(hA);  wB = __low2float(hB);  }
            } else {
                wA = __low2float(w24);
                wB = __high2float(w24);
            }
            acc0 += wA * v[dx];     ws0 += wA;
            acc1 += wB * v[dx + 1]; ws1 += wB;
        }
    }

    float2 m = *reinterpret_cast<const float2*>(mask + (size_t)b * HWSZ + pix);
    float2 res;
    res.x = __fdividef(acc0, ws0) * m.x;
    res.y = __fdividef(acc1, ws1) * m.y;

    float* xo = writeOut ? out : g_x[1 - src];
    *reinterpret_cast<float2*>(xo + (size_t)b * HWSZ + pix) = res;
}

// ---------------------------------------------------------------------------
extern "C" void kernel_launch(void* const* d_in, const int* in_sizes, int n_in,
                              void* d_out, int out_size)
{
    const float* img  = (const float*)d_in[0];
    const float* feat = (const float*)d_in[1];
    const float* mask = (const float*)d_in[2];
    float* out = (float*)d_out;

    dim3 pblk(PTX, PTY);
    dim3 pgrd(WW / PTX, HH / PTY, BB);    // (12, 24, 4)
    precompute_kernel<<<pgrd, pblk>>>(img, feat, mask);

    dim3 iblk(TXV, TYV);
    dim3 igrd(WW / PW, HH / TYV, BB);     // (6, 24, 4) = 576 blocks
    for (int i = 0; i < NUM_ITER; i++) {
        int src = i & 1;
        int writeOut = (i == NUM_ITER - 1) ? 1 : 0;
        iter_kernel<<<igrd, iblk>>>(mask, out, src, writeOut);
    }
}